// round 12
// baseline (speedup 1.0000x reference)
#include <cuda_runtime.h>
#include <cuda_bf16.h>

#define N_NODES 50000
#define N_EDGES 800000
#define F 64
#define G 512
#define OUTD 32
#define CAP 64   // ELL capacity per node (mean deg=16; Poisson tail @64 ~ 1e-20)

typedef unsigned long long u64;

// Scratch (device globals). 16B-aligned for red.v4 / float4.
__device__ __align__(16) float g_hs[N_NODES * F];   // (X @ W) * inv[row]
__device__ __align__(16) float g_hr[N_NODES * F];   // layer-1 output (relu'd)
__device__ float g_inv[N_NODES];
__device__ int   g_cur[N_NODES];          // fill cursors -> final degree
__device__ int   g_ell[N_NODES * CAP];    // ELL: src indices per dst node
__device__ __align__(16) float g_psum[G * F];
__device__ int   g_pcnt[G];

// ---------------- init ----------------
__global__ void k_init(int* cur, float* psum, int* pcnt) {
    int i = blockIdx.x * blockDim.x + threadIdx.x;
    if (i < N_NODES) cur[i] = 0;
    if (i < G * F)   psum[i] = 0.0f;
    if (i < G)       pcnt[i] = 0;
}

// ---------------- ELL fill: one pass computes degree AND placement ----------
__global__ void k_fill(const int4* __restrict__ src4, const int4* __restrict__ dst4,
                       int* cur, int* ell) {
    int t = blockIdx.x * 256 + threadIdx.x;
    if (t >= N_EDGES / 8) return;
    int4 sa = src4[2 * t];
    int4 sb = src4[2 * t + 1];
    int4 da = dst4[2 * t];
    int4 db = dst4[2 * t + 1];
    int p0 = atomicAdd(&cur[da.x], 1);
    int p1 = atomicAdd(&cur[da.y], 1);
    int p2 = atomicAdd(&cur[da.z], 1);
    int p3 = atomicAdd(&cur[da.w], 1);
    int p4 = atomicAdd(&cur[db.x], 1);
    int p5 = atomicAdd(&cur[db.y], 1);
    int p6 = atomicAdd(&cur[db.z], 1);
    int p7 = atomicAdd(&cur[db.w], 1);
    if (p0 < CAP) ell[da.x * CAP + p0] = sa.x;
    if (p1 < CAP) ell[da.y * CAP + p1] = sa.y;
    if (p2 < CAP) ell[da.z * CAP + p2] = sa.z;
    if (p3 < CAP) ell[da.w * CAP + p3] = sa.w;
    if (p4 < CAP) ell[db.x * CAP + p4] = sb.x;
    if (p5 < CAP) ell[db.y * CAP + p5] = sb.y;
    if (p6 < CAP) ell[db.z * CAP + p6] = sb.z;
    if (p7 < CAP) ell[db.w * CAP + p7] = sb.w;
}

// ---------------- norms + per-graph counts ----------------
__global__ void k_inv(const int* __restrict__ cur, float* inv,
                      const int* __restrict__ batch, int* pcnt) {
    int i = blockIdx.x * 256 + threadIdx.x;
    if (i >= N_NODES) return;
    inv[i] = rsqrtf((float)cur[i] + 1.0f);
    atomicAdd(&pcnt[batch[i]], 1);
}

// ---------------- GEMM: hs[r,:] = (in[r,:] @ W) * inv[r] ----------------
// 256 threads, 64 rows/block (smem ~34KB -> 6 CTAs/SM, 48 warps).
// Thread: 2 rows (rowt, rowt+32) x 8 cols, FFMA2 packed math.
#define XPAD 68
__global__ void __launch_bounds__(256, 6)
k_gemm(const float* __restrict__ Xin,
       const float* __restrict__ Wm, const float* __restrict__ inv,
       float* __restrict__ hs) {
    __shared__ float Ws[F * F];          // 16 KB
    __shared__ float Xs[64 * XPAD];      // 17.4 KB
    int t = threadIdx.x;
    int rowbase = blockIdx.x * 64;

    for (int i = t; i < F * F; i += 256) Ws[i] = Wm[i];

#pragma unroll
    for (int it = 0; it < 4; it++) {
        int f  = t + it * 256;       // float4 idx 0..1023
        int r  = f >> 4;             // 0..63
        int c4 = (f & 15) * 4;
        int gr = rowbase + r;
        float4 v = make_float4(0.f, 0.f, 0.f, 0.f);
        if (gr < N_NODES) v = *reinterpret_cast<const float4*>(&Xin[gr * F + c4]);
        *reinterpret_cast<float4*>(&Xs[r * XPAD + c4]) = v;
    }
    __syncthreads();

    int colg = (t & 7) * 8;     // 8 output cols
    int rowt = (t >> 3);        // rows: rowt, rowt+32

    u64 acc[2][4];
#pragma unroll
    for (int i = 0; i < 2; i++)
#pragma unroll
        for (int j = 0; j < 4; j++) acc[i][j] = 0ull;

#pragma unroll
    for (int k0 = 0; k0 < F; k0 += 4) {
        float4 xq[2];
        xq[0] = *reinterpret_cast<const float4*>(&Xs[rowt * XPAD + k0]);
        xq[1] = *reinterpret_cast<const float4*>(&Xs[(rowt + 32) * XPAD + k0]);
#pragma unroll
        for (int kk = 0; kk < 4; kk++) {
            int k = k0 + kk;
            ulonglong2 wa = *reinterpret_cast<const ulonglong2*>(&Ws[k * F + colg]);
            ulonglong2 wb = *reinterpret_cast<const ulonglong2*>(&Ws[k * F + colg + 4]);
#pragma unroll
            for (int i = 0; i < 2; i++) {
                float xv = (kk == 0) ? xq[i].x : (kk == 1) ? xq[i].y
                         : (kk == 2) ? xq[i].z : xq[i].w;
                u64 xx;
                asm("mov.b64 %0, {%1, %1};" : "=l"(xx) : "r"(__float_as_uint(xv)));
                asm("fma.rn.f32x2 %0, %1, %2, %0;" : "+l"(acc[i][0]) : "l"(xx), "l"(wa.x));
                asm("fma.rn.f32x2 %0, %1, %2, %0;" : "+l"(acc[i][1]) : "l"(xx), "l"(wa.y));
                asm("fma.rn.f32x2 %0, %1, %2, %0;" : "+l"(acc[i][2]) : "l"(xx), "l"(wb.x));
                asm("fma.rn.f32x2 %0, %1, %2, %0;" : "+l"(acc[i][3]) : "l"(xx), "l"(wb.y));
            }
        }
    }

#pragma unroll
    for (int i = 0; i < 2; i++) {
        int gr = rowbase + rowt + 32 * i;
        if (gr < N_NODES) {
            float s = inv[gr];
            float2 p0 = *reinterpret_cast<float2*>(&acc[i][0]);
            float2 p1 = *reinterpret_cast<float2*>(&acc[i][1]);
            float2 p2 = *reinterpret_cast<float2*>(&acc[i][2]);
            float2 p3 = *reinterpret_cast<float2*>(&acc[i][3]);
            float4 o0 = make_float4(p0.x * s, p0.y * s, p1.x * s, p1.y * s);
            float4 o1 = make_float4(p2.x * s, p2.y * s, p3.x * s, p3.y * s);
            *reinterpret_cast<float4*>(&hs[gr * F + colg])     = o0;
            *reinterpret_cast<float4*>(&hs[gr * F + colg + 4]) = o1;
        }
    }
}

// ---------------- gather-aggregate + epilogue ----------------
// out[n] = relu( inv[n] * (sum_{s in N(n)} hs[s] + hs[n]) + bias )
template<bool POOL>
__global__ void __launch_bounds__(256)
k_agg(const float* __restrict__ hs, const int* __restrict__ ell,
      const int* __restrict__ deg,
      const float* __restrict__ inv, const float* __restrict__ bias,
      const int* __restrict__ batch,
      float* __restrict__ outbuf, float* __restrict__ psum) {
    unsigned t = blockIdx.x * 256u + threadIdx.x;
    unsigned n = t >> 4;
    if (n >= N_NODES) return;
    int q = (t & 15) * 4;

    float4 acc = *reinterpret_cast<const float4*>(&hs[n * F + q]);  // self term

    int cnt = deg[n];
    if (cnt > CAP) cnt = CAP;
    const int* lst = ell + n * CAP;

    int j = 0;
    for (; j + 1 < cnt; j += 2) {
        int s0 = lst[j];
        int s1 = lst[j + 1];
        float4 v0 = *reinterpret_cast<const float4*>(&hs[s0 * F + q]);
        float4 v1 = *reinterpret_cast<const float4*>(&hs[s1 * F + q]);
        acc.x += v0.x + v1.x;
        acc.y += v0.y + v1.y;
        acc.z += v0.z + v1.z;
        acc.w += v0.w + v1.w;
    }
    if (j < cnt) {
        int s0 = lst[j];
        float4 v0 = *reinterpret_cast<const float4*>(&hs[s0 * F + q]);
        acc.x += v0.x; acc.y += v0.y; acc.z += v0.z; acc.w += v0.w;
    }

    float iv = inv[n];
    float4 o;
    o.x = fmaxf(acc.x * iv + bias[q + 0], 0.f);
    o.y = fmaxf(acc.y * iv + bias[q + 1], 0.f);
    o.z = fmaxf(acc.z * iv + bias[q + 2], 0.f);
    o.w = fmaxf(acc.w * iv + bias[q + 3], 0.f);

    if (POOL) {
        int g = batch[n];
        float* p = &psum[g * F + q];
        asm volatile("red.global.add.v4.f32 [%0], {%1, %2, %3, %4};"
                     :: "l"(p), "f"(o.x), "f"(o.y), "f"(o.z), "f"(o.w)
                     : "memory");
    } else {
        *reinterpret_cast<float4*>(&outbuf[n * F + q]) = o;
    }
}

// ---------------- final FC ----------------
__global__ void k_fc(const float* __restrict__ fcW, const float* __restrict__ fcb,
                     const float* __restrict__ psum, const int* __restrict__ pcnt,
                     float* __restrict__ out) {
    int t = blockIdx.x * blockDim.x + threadIdx.x;
    if (t >= G * OUTD) return;
    int g = t / OUTD;
    int o = t % OUTD;
    float cnt = fmaxf((float)pcnt[g], 1.0f);
    float invc = 1.0f / cnt;
    float acc = fcb[o];
#pragma unroll
    for (int k = 0; k < F; k++)
        acc += psum[g * F + k] * invc * fcW[k * OUTD + o];
    out[t] = acc;
}

extern "C" void kernel_launch(void* const* d_in, const int* in_sizes, int n_in,
                              void* d_out, int out_size) {
    const float* x   = (const float*)d_in[0];
    const float* W1  = (const float*)d_in[1];
    const float* b1  = (const float*)d_in[2];
    const float* W2  = (const float*)d_in[3];
    const float* b2  = (const float*)d_in[4];
    const float* fcW = (const float*)d_in[5];
    const float* fcb = (const float*)d_in[6];
    const int* edge_index = (const int*)d_in[7];  // int32 (JAX x64 disabled)
    const int* batch      = (const int*)d_in[8];
    float* out = (float*)d_out;

    const int4* src4 = (const int4*)edge_index;
    const int4* dst4 = (const int4*)(edge_index + N_EDGES);

    float *p_hs, *p_hr, *p_inv, *p_psum;
    int *p_cur, *p_ell, *p_pcnt;
    cudaGetSymbolAddress((void**)&p_hs,   g_hs);
    cudaGetSymbolAddress((void**)&p_hr,   g_hr);
    cudaGetSymbolAddress((void**)&p_inv,  g_inv);
    cudaGetSymbolAddress((void**)&p_psum, g_psum);
    cudaGetSymbolAddress((void**)&p_cur,  g_cur);
    cudaGetSymbolAddress((void**)&p_ell,  g_ell);
    cudaGetSymbolAddress((void**)&p_pcnt, g_pcnt);

    const int gridN        = (N_NODES + 255) / 256;          // 196
    const int gridFill     = (N_EDGES / 8 + 255) / 256;      // 391
    const int gridNodeQuad = (N_NODES * 16 + 255) / 256;     // 3125
    const int gridGemm     = (N_NODES + 63) / 64;            // 782

    // ELL build + norms (one atomic pass over edges)
    k_init<<<gridN, 256>>>(p_cur, p_psum, p_pcnt);
    k_fill<<<gridFill, 256>>>(src4, dst4, p_cur, p_ell);
    k_inv<<<gridN, 256>>>(p_cur, p_inv, batch, p_pcnt);

    // layer 1
    k_gemm<<<gridGemm, 256>>>(x, W1, p_inv, p_hs);
    k_agg<false><<<gridNodeQuad, 256>>>(p_hs, p_ell, p_cur, p_inv, b1,
                                        batch, p_hr, p_psum);
    // layer 2
    k_gemm<<<gridGemm, 256>>>(p_hr, W2, p_inv, p_hs);
    k_agg<true><<<gridNodeQuad, 256>>>(p_hs, p_ell, p_cur, p_inv, b2,
                                       batch, nullptr, p_psum);

    // fc
    k_fc<<<(G * OUTD + 255) / 256, 256>>>(fcW, fcb, p_psum, p_pcnt, out);
}

// round 13
// speedup vs baseline: 1.6303x; 1.6303x over previous
#include <cuda_runtime.h>
#include <cuda_bf16.h>
#include <cstdint>

#define N_NODES 50000
#define N_EDGES 800000
#define F 64
#define G 512
#define OUTD 32
#define CAP 64   // ELL capacity per node (mean deg=16; Poisson tail @64 ~ 1e-20)

// Scratch (device globals). 16B-aligned for red.v4 / float4.
__device__ __align__(16) float g_hs[N_NODES * F];   // (X @ W) * inv[row]
__device__ __align__(16) float g_hr[N_NODES * F];   // layer-1 output (relu'd)
__device__ float g_inv[N_NODES];
__device__ int   g_cur[N_NODES];          // fill cursors -> final degree
__device__ int   g_ell[N_NODES * CAP];    // ELL: src indices per dst node
__device__ __align__(16) float g_psum[G * F];
__device__ int   g_pcnt[G];

// ---------------- init ----------------
__global__ void k_init(int* cur, float* psum, int* pcnt) {
    int i = blockIdx.x * blockDim.x + threadIdx.x;
    if (i < N_NODES) cur[i] = 0;
    if (i < G * F)   psum[i] = 0.0f;
    if (i < G)       pcnt[i] = 0;
}

// ---------------- ELL fill: one pass computes degree AND placement ----------
__global__ void k_fill(const int4* __restrict__ src4, const int4* __restrict__ dst4,
                       int* cur, int* ell) {
    int t = blockIdx.x * 256 + threadIdx.x;
    if (t >= N_EDGES / 8) return;
    int4 sa = src4[2 * t];
    int4 sb = src4[2 * t + 1];
    int4 da = dst4[2 * t];
    int4 db = dst4[2 * t + 1];
    int p0 = atomicAdd(&cur[da.x], 1);
    int p1 = atomicAdd(&cur[da.y], 1);
    int p2 = atomicAdd(&cur[da.z], 1);
    int p3 = atomicAdd(&cur[da.w], 1);
    int p4 = atomicAdd(&cur[db.x], 1);
    int p5 = atomicAdd(&cur[db.y], 1);
    int p6 = atomicAdd(&cur[db.z], 1);
    int p7 = atomicAdd(&cur[db.w], 1);
    if (p0 < CAP) ell[da.x * CAP + p0] = sa.x;
    if (p1 < CAP) ell[da.y * CAP + p1] = sa.y;
    if (p2 < CAP) ell[da.z * CAP + p2] = sa.z;
    if (p3 < CAP) ell[da.w * CAP + p3] = sa.w;
    if (p4 < CAP) ell[db.x * CAP + p4] = sb.x;
    if (p5 < CAP) ell[db.y * CAP + p5] = sb.y;
    if (p6 < CAP) ell[db.z * CAP + p6] = sb.z;
    if (p7 < CAP) ell[db.w * CAP + p7] = sb.w;
}

// ---------------- norms + per-graph counts ----------------
__global__ void k_inv(const int* __restrict__ cur, float* inv,
                      const int* __restrict__ batch, int* pcnt) {
    int i = blockIdx.x * 256 + threadIdx.x;
    if (i >= N_NODES) return;
    inv[i] = rsqrtf((float)cur[i] + 1.0f);
    atomicAdd(&pcnt[batch[i]], 1);
}

// ---------------- GEMM (TF32 tensor cores): hs = (X @ W) * inv[row] --------
// mma.sync.m16n8k8 tf32. 256 thr = 8 warps; warp = 16 rows x 64 cols.
// XPAD=68: A-frag bank = (4*row + k) % 32 -> conflict-free.
// WPAD=72: B-frag bank = (8*k + n) % 32  -> conflict-free.
#define XPAD 68
#define WPAD 72

__device__ __forceinline__ uint32_t f2tf32(float v) {
    uint32_t r;
    asm("cvt.rna.tf32.f32 %0, %1;" : "=r"(r) : "f"(v));
    return r;
}

__global__ void __launch_bounds__(256)
k_gemm(const float* __restrict__ Xin,
       const float* __restrict__ Wm, const float* __restrict__ inv,
       float* __restrict__ hs) {
    __shared__ float Ws[F * WPAD];       // 18.4 KB
    __shared__ float Xs[128 * XPAD];     // 34.8 KB
    int t = threadIdx.x;
    int rowbase = blockIdx.x * 128;

    // fill Ws (64x64 -> padded 72)
#pragma unroll
    for (int it = 0; it < 4; it++) {
        int f  = t + it * 256;           // float4 idx 0..1023
        int k  = f >> 4;
        int n4 = (f & 15) * 4;
        float4 w = *reinterpret_cast<const float4*>(&Wm[k * F + n4]);
        *reinterpret_cast<float4*>(&Ws[k * WPAD + n4]) = w;
    }
    // fill Xs (128 rows x 64 -> padded 68)
#pragma unroll
    for (int it = 0; it < 8; it++) {
        int f  = t + it * 256;
        int r  = f >> 4;
        int c4 = (f & 15) * 4;
        int gr = rowbase + r;
        float4 v = make_float4(0.f, 0.f, 0.f, 0.f);
        if (gr < N_NODES) v = *reinterpret_cast<const float4*>(&Xin[gr * F + c4]);
        *reinterpret_cast<float4*>(&Xs[r * XPAD + c4]) = v;
    }
    __syncthreads();

    int w    = t >> 5;
    int lane = t & 31;
    int g    = lane >> 2;   // groupID (0..7)
    int tg   = lane & 3;    // thread-in-group (0..3)
    int rw   = w * 16;      // warp row base within tile

    float acc[8][4];
#pragma unroll
    for (int nt = 0; nt < 8; nt++)
#pragma unroll
        for (int j = 0; j < 4; j++) acc[nt][j] = 0.f;

    const float* xr0 = &Xs[(rw + g) * XPAD];
    const float* xr1 = &Xs[(rw + g + 8) * XPAD];

#pragma unroll
    for (int k0 = 0; k0 < F; k0 += 8) {
        uint32_t a0 = f2tf32(xr0[k0 + tg]);
        uint32_t a1 = f2tf32(xr1[k0 + tg]);
        uint32_t a2 = f2tf32(xr0[k0 + tg + 4]);
        uint32_t a3 = f2tf32(xr1[k0 + tg + 4]);
        const float* wr0 = &Ws[(k0 + tg) * WPAD + g];
        const float* wr1 = &Ws[(k0 + tg + 4) * WPAD + g];
#pragma unroll
        for (int nt = 0; nt < 8; nt++) {
            uint32_t b0 = f2tf32(wr0[nt * 8]);
            uint32_t b1 = f2tf32(wr1[nt * 8]);
            asm volatile(
                "mma.sync.aligned.m16n8k8.row.col.f32.tf32.tf32.f32 "
                "{%0,%1,%2,%3}, {%4,%5,%6,%7}, {%8,%9}, {%0,%1,%2,%3};\n"
                : "+f"(acc[nt][0]), "+f"(acc[nt][1]),
                  "+f"(acc[nt][2]), "+f"(acc[nt][3])
                : "r"(a0), "r"(a1), "r"(a2), "r"(a3), "r"(b0), "r"(b1));
        }
    }

    // epilogue: scale by inv[row], write float2 per (row, n-tile)
    int row0 = rowbase + rw + g;
    int row1 = row0 + 8;
    float s0 = (row0 < N_NODES) ? inv[row0] : 0.f;
    float s1 = (row1 < N_NODES) ? inv[row1] : 0.f;
#pragma unroll
    for (int nt = 0; nt < 8; nt++) {
        int c = nt * 8 + tg * 2;
        if (row0 < N_NODES) {
            float2 o = make_float2(acc[nt][0] * s0, acc[nt][1] * s0);
            *reinterpret_cast<float2*>(&hs[row0 * F + c]) = o;
        }
        if (row1 < N_NODES) {
            float2 o = make_float2(acc[nt][2] * s1, acc[nt][3] * s1);
            *reinterpret_cast<float2*>(&hs[row1 * F + c]) = o;
        }
    }
}

// ---------------- gather-aggregate + epilogue ----------------
// out[n] = relu( inv[n] * (sum_{s in N(n)} hs[s] + hs[n]) + bias )
template<bool POOL>
__global__ void __launch_bounds__(256)
k_agg(const float* __restrict__ hs, const int* __restrict__ ell,
      const int* __restrict__ deg,
      const float* __restrict__ inv, const float* __restrict__ bias,
      const int* __restrict__ batch,
      float* __restrict__ outbuf, float* __restrict__ psum) {
    unsigned t = blockIdx.x * 256u + threadIdx.x;
    unsigned n = t >> 4;
    if (n >= N_NODES) return;
    int q = (t & 15) * 4;

    float4 acc = *reinterpret_cast<const float4*>(&hs[n * F + q]);  // self term

    int cnt = deg[n];
    if (cnt > CAP) cnt = CAP;
    const int* lst = ell + n * CAP;

    int j = 0;
    for (; j + 1 < cnt; j += 2) {
        int s0 = lst[j];
        int s1 = lst[j + 1];
        float4 v0 = *reinterpret_cast<const float4*>(&hs[s0 * F + q]);
        float4 v1 = *reinterpret_cast<const float4*>(&hs[s1 * F + q]);
        acc.x += v0.x + v1.x;
        acc.y += v0.y + v1.y;
        acc.z += v0.z + v1.z;
        acc.w += v0.w + v1.w;
    }
    if (j < cnt) {
        int s0 = lst[j];
        float4 v0 = *reinterpret_cast<const float4*>(&hs[s0 * F + q]);
        acc.x += v0.x; acc.y += v0.y; acc.z += v0.z; acc.w += v0.w;
    }

    float iv = inv[n];
    float4 o;
    o.x = fmaxf(acc.x * iv + bias[q + 0], 0.f);
    o.y = fmaxf(acc.y * iv + bias[q + 1], 0.f);
    o.z = fmaxf(acc.z * iv + bias[q + 2], 0.f);
    o.w = fmaxf(acc.w * iv + bias[q + 3], 0.f);

    if (POOL) {
        int g = batch[n];
        float* p = &psum[g * F + q];
        asm volatile("red.global.add.v4.f32 [%0], {%1, %2, %3, %4};"
                     :: "l"(p), "f"(o.x), "f"(o.y), "f"(o.z), "f"(o.w)
                     : "memory");
    } else {
        *reinterpret_cast<float4*>(&outbuf[n * F + q]) = o;
    }
}

// ---------------- final FC ----------------
__global__ void k_fc(const float* __restrict__ fcW, const float* __restrict__ fcb,
                     const float* __restrict__ psum, const int* __restrict__ pcnt,
                     float* __restrict__ out) {
    int t = blockIdx.x * blockDim.x + threadIdx.x;
    if (t >= G * OUTD) return;
    int g = t / OUTD;
    int o = t % OUTD;
    float cnt = fmaxf((float)pcnt[g], 1.0f);
    float invc = 1.0f / cnt;
    float acc = fcb[o];
#pragma unroll
    for (int k = 0; k < F; k++)
        acc += psum[g * F + k] * invc * fcW[k * OUTD + o];
    out[t] = acc;
}

extern "C" void kernel_launch(void* const* d_in, const int* in_sizes, int n_in,
                              void* d_out, int out_size) {
    const float* x   = (const float*)d_in[0];
    const float* W1  = (const float*)d_in[1];
    const float* b1  = (const float*)d_in[2];
    const float* W2  = (const float*)d_in[3];
    const float* b2  = (const float*)d_in[4];
    const float* fcW = (const float*)d_in[5];
    const float* fcb = (const float*)d_in[6];
    const int* edge_index = (const int*)d_in[7];  // int32 (JAX x64 disabled)
    const int* batch      = (const int*)d_in[8];
    float* out = (float*)d_out;

    const int4* src4 = (const int4*)edge_index;
    const int4* dst4 = (const int4*)(edge_index + N_EDGES);

    float *p_hs, *p_hr, *p_inv, *p_psum;
    int *p_cur, *p_ell, *p_pcnt;
    cudaGetSymbolAddress((void**)&p_hs,   g_hs);
    cudaGetSymbolAddress((void**)&p_hr,   g_hr);
    cudaGetSymbolAddress((void**)&p_inv,  g_inv);
    cudaGetSymbolAddress((void**)&p_psum, g_psum);
    cudaGetSymbolAddress((void**)&p_cur,  g_cur);
    cudaGetSymbolAddress((void**)&p_ell,  g_ell);
    cudaGetSymbolAddress((void**)&p_pcnt, g_pcnt);

    const int gridN        = (N_NODES + 255) / 256;          // 196
    const int gridFill     = (N_EDGES / 8 + 255) / 256;      // 391
    const int gridNodeQuad = (N_NODES * 16 + 255) / 256;     // 3125
    const int gridGemm     = (N_NODES + 127) / 128;          // 391

    // ELL build + norms (one atomic pass over edges)
    k_init<<<gridN, 256>>>(p_cur, p_psum, p_pcnt);
    k_fill<<<gridFill, 256>>>(src4, dst4, p_cur, p_ell);
    k_inv<<<gridN, 256>>>(p_cur, p_inv, batch, p_pcnt);

    // layer 1
    k_gemm<<<gridGemm, 256>>>(x, W1, p_inv, p_hs);
    k_agg<false><<<gridNodeQuad, 256>>>(p_hs, p_ell, p_cur, p_inv, b1,
                                        batch, p_hr, p_psum);
    // layer 2
    k_gemm<<<gridGemm, 256>>>(p_hr, W2, p_inv, p_hs);
    k_agg<true><<<gridNodeQuad, 256>>>(p_hs, p_ell, p_cur, p_inv, b2,
                                       batch, nullptr, p_psum);

    // fc
    k_fc<<<(G * OUTD + 255) / 256, 256>>>(fcW, fcb, p_psum, p_pcnt, out);
}